// round 1
// baseline (speedup 1.0000x reference)
#include <cuda_runtime.h>
#include <math.h>

#define N_NODES 20000
#define N_EDGES 256000
#define ET (N_EDGES + N_NODES)   // with self loops = 276000
#define N_GRAPHS 512
#define F_IN 75
#define HEADS 10
#define HF (HEADS * F_IN)        // 750
#define OUT_DIM 128

// ---------------- scratch (device globals; re-initialized every launch) ----
__device__ float g_h1[(size_t)N_NODES * HF];       // x@W1            60 MB
__device__ float g_as1[N_NODES * HEADS];
__device__ float g_ad1[N_NODES * HEADS];
__device__ float g_emax1[N_NODES * HEADS];
__device__ float g_den1[N_NODES * HEADS];
__device__ float g_w1[(size_t)ET * HEADS];         // exp weights     11 MB
__device__ float g_out1[(size_t)N_NODES * HF];     // gat1 out        60 MB
__device__ float g_h2[(size_t)N_NODES * OUT_DIM];  // out1@W2         10 MB
__device__ float g_as2[N_NODES];
__device__ float g_ad2[N_NODES];
__device__ float g_emax2[N_NODES];
__device__ float g_den2[N_NODES];
__device__ float g_w2[ET];
__device__ float g_out2[(size_t)N_NODES * OUT_DIM];
__device__ float g_pool[N_GRAPHS * OUT_DIM];

// ---------------- helpers ---------------------------------------------------
__device__ __forceinline__ void edge_sd(const int* __restrict__ ei, int e,
                                        int& s, int& d) {
    if (e < N_EDGES) { s = ei[e]; d = ei[N_EDGES + e]; }
    else             { s = e - N_EDGES; d = s; }
}

__device__ __forceinline__ float leaky(float x) {
    return x > 0.f ? x : 0.2f * x;
}

__device__ __forceinline__ void atomicMaxF(float* addr, float val) {
    int* ia = (int*)addr;
    int old = *ia;
    while (__int_as_float(old) < val) {
        int assumed = old;
        old = atomicCAS(ia, assumed, __float_as_int(val));
        if (old == assumed) break;
    }
}

__global__ void fill_kernel(float* p, float v, int n) {
    int i = blockIdx.x * blockDim.x + threadIdx.x;
    if (i < n) p[i] = v;
}

// ---------------- GEMM: C[M,N] = A[M,K] @ B[K,N] ---------------------------
// 64x64 tile, BK=16, 4x4 register micro-tile, 256 threads, float4 smem reads.
#define BM 64
#define BN 64
#define BKK 16
__global__ __launch_bounds__(256) void gemm64(
    const float* __restrict__ A, const float* __restrict__ B,
    float* __restrict__ C, int M, int N, int K) {
    __shared__ float As[BKK][BM];   // As[k][m]
    __shared__ float Bs[BKK][BN];   // Bs[k][n]
    int bm = blockIdx.y * BM, bn = blockIdx.x * BN;
    int tid = threadIdx.x;
    int tm = (tid / 16) * 4, tn = (tid % 16) * 4;
    float acc[4][4] = {};
    for (int k0 = 0; k0 < K; k0 += BKK) {
        // load A tile (BM x BKK), store transposed
        #pragma unroll
        for (int i = tid; i < BM * BKK; i += 256) {
            int m = i / BKK, k = i % BKK;
            float v = 0.f;
            if (bm + m < M && k0 + k < K) v = A[(size_t)(bm + m) * K + k0 + k];
            As[k][m] = v;
        }
        // load B tile (BKK x BN)
        #pragma unroll
        for (int i = tid; i < BKK * BN; i += 256) {
            int k = i / BN, n = i % BN;
            float v = 0.f;
            if (k0 + k < K && bn + n < N) v = B[(size_t)(k0 + k) * N + bn + n];
            Bs[k][n] = v;
        }
        __syncthreads();
        #pragma unroll
        for (int k = 0; k < BKK; k++) {
            float4 a4 = *reinterpret_cast<const float4*>(&As[k][tm]);
            float4 b4 = *reinterpret_cast<const float4*>(&Bs[k][tn]);
            float a[4] = {a4.x, a4.y, a4.z, a4.w};
            float b[4] = {b4.x, b4.y, b4.z, b4.w};
            #pragma unroll
            for (int i = 0; i < 4; i++)
                #pragma unroll
                for (int j = 0; j < 4; j++)
                    acc[i][j] += a[i] * b[j];
        }
        __syncthreads();
    }
    #pragma unroll
    for (int i = 0; i < 4; i++) {
        int m = bm + tm + i;
        if (m >= M) continue;
        #pragma unroll
        for (int j = 0; j < 4; j++) {
            int n = bn + tn + j;
            if (n < N) C[(size_t)m * N + n] = acc[i][j];
        }
    }
}

// ---------------- layer 1 attention pieces ---------------------------------
// warp per node: alpha_src / alpha_dst for all 10 heads
__global__ void alpha1_kernel(const float* __restrict__ a_src,
                              const float* __restrict__ a_dst) {
    int warp = (blockIdx.x * blockDim.x + threadIdx.x) >> 5;
    int lane = threadIdx.x & 31;
    if (warp >= N_NODES) return;
    const float* row = g_h1 + (size_t)warp * HF;
    for (int h = 0; h < HEADS; h++) {
        float s = 0.f, d = 0.f;
        for (int f = lane; f < F_IN; f += 32) {
            float v = row[h * F_IN + f];
            s += v * a_src[h * F_IN + f];
            d += v * a_dst[h * F_IN + f];
        }
        #pragma unroll
        for (int o = 16; o > 0; o >>= 1) {
            s += __shfl_down_sync(~0u, s, o);
            d += __shfl_down_sync(~0u, d, o);
        }
        if (lane == 0) {
            g_as1[warp * HEADS + h] = s;
            g_ad1[warp * HEADS + h] = d;
        }
    }
}

__global__ void edge_max1(const int* __restrict__ ei) {
    int t = blockIdx.x * blockDim.x + threadIdx.x;
    if (t >= ET * HEADS) return;
    int e = t / HEADS, h = t - e * HEADS;
    int s, d; edge_sd(ei, e, s, d);
    float v = leaky(g_as1[s * HEADS + h] + g_ad1[d * HEADS + h]);
    atomicMaxF(&g_emax1[d * HEADS + h], v);
}

__global__ void edge_exp1(const int* __restrict__ ei) {
    int t = blockIdx.x * blockDim.x + threadIdx.x;
    if (t >= ET * HEADS) return;
    int e = t / HEADS, h = t - e * HEADS;
    int s, d; edge_sd(ei, e, s, d);
    float v = leaky(g_as1[s * HEADS + h] + g_ad1[d * HEADS + h]);
    float w = expf(v - g_emax1[d * HEADS + h]);
    g_w1[t] = w;
    atomicAdd(&g_den1[d * HEADS + h], w);
}

// block per edge: out1[dst] += h1[src] * alpha   (750 feats, 10 heads)
__global__ __launch_bounds__(256) void scatter1(const int* __restrict__ ei) {
    int e = blockIdx.x;
    int s, d; edge_sd(ei, e, s, d);
    __shared__ float alpha[HEADS];
    if (threadIdx.x < HEADS)
        alpha[threadIdx.x] = g_w1[(size_t)e * HEADS + threadIdx.x] /
                             (g_den1[d * HEADS + threadIdx.x] + 1e-16f);
    __syncthreads();
    const float* hr = g_h1 + (size_t)s * HF;
    float* orow = g_out1 + (size_t)d * HF;
    for (int f = threadIdx.x; f < HF; f += 256)
        atomicAdd(&orow[f], hr[f] * alpha[f / F_IN]);
}

__global__ void elu1_kernel(const float* __restrict__ b1) {
    int t = blockIdx.x * blockDim.x + threadIdx.x;
    if (t >= N_NODES * HF) return;
    float v = g_out1[t] + b1[t % HF];
    g_out1[t] = v > 0.f ? v : expf(v) - 1.f;
}

// ---------------- layer 2 attention pieces ---------------------------------
__global__ void alpha2_kernel(const float* __restrict__ a_src,
                              const float* __restrict__ a_dst) {
    int warp = (blockIdx.x * blockDim.x + threadIdx.x) >> 5;
    int lane = threadIdx.x & 31;
    if (warp >= N_NODES) return;
    const float* row = g_h2 + (size_t)warp * OUT_DIM;
    float s = 0.f, d = 0.f;
    #pragma unroll
    for (int f = lane; f < OUT_DIM; f += 32) {
        float v = row[f];
        s += v * a_src[f];
        d += v * a_dst[f];
    }
    #pragma unroll
    for (int o = 16; o > 0; o >>= 1) {
        s += __shfl_down_sync(~0u, s, o);
        d += __shfl_down_sync(~0u, d, o);
    }
    if (lane == 0) { g_as2[warp] = s; g_ad2[warp] = d; }
}

__global__ void edge_max2(const int* __restrict__ ei) {
    int e = blockIdx.x * blockDim.x + threadIdx.x;
    if (e >= ET) return;
    int s, d; edge_sd(ei, e, s, d);
    atomicMaxF(&g_emax2[d], leaky(g_as2[s] + g_ad2[d]));
}

__global__ void edge_exp2(const int* __restrict__ ei) {
    int e = blockIdx.x * blockDim.x + threadIdx.x;
    if (e >= ET) return;
    int s, d; edge_sd(ei, e, s, d);
    float w = expf(leaky(g_as2[s] + g_ad2[d]) - g_emax2[d]);
    g_w2[e] = w;
    atomicAdd(&g_den2[d], w);
}

__global__ __launch_bounds__(128) void scatter2(const int* __restrict__ ei) {
    int e = blockIdx.x;
    int s, d; edge_sd(ei, e, s, d);
    float alpha = g_w2[e] / (g_den2[d] + 1e-16f);
    int f = threadIdx.x;
    atomicAdd(&g_out2[(size_t)d * OUT_DIM + f],
              g_h2[(size_t)s * OUT_DIM + f] * alpha);
}

// relu(out2 + b2) then per-graph max pool (nonneg -> int atomicMax is valid)
__global__ void pool_kernel(const float* __restrict__ b2,
                            const int* __restrict__ batch) {
    int t = blockIdx.x * blockDim.x + threadIdx.x;
    if (t >= N_NODES * OUT_DIM) return;
    int n = t >> 7, f = t & 127;
    float v = g_out2[t] + b2[f];
    v = v > 0.f ? v : 0.f;
    int gi = batch[n];
    atomicMax((int*)&g_pool[gi * OUT_DIM + f], __float_as_int(v));
}

// out = relu(pool @ Wg + bg), one block per graph
__global__ __launch_bounds__(128) void final_kernel(
    const float* __restrict__ Wg, const float* __restrict__ bg,
    float* __restrict__ out) {
    __shared__ float gr[OUT_DIM];
    int gi = blockIdx.x, j = threadIdx.x;
    gr[j] = g_pool[gi * OUT_DIM + j];
    __syncthreads();
    float acc = bg[j];
    #pragma unroll 8
    for (int k = 0; k < OUT_DIM; k++)
        acc += gr[k] * Wg[k * OUT_DIM + j];
    out[gi * OUT_DIM + j] = acc > 0.f ? acc : 0.f;
}

// ---------------- launch ----------------------------------------------------
extern "C" void kernel_launch(void* const* d_in, const int* in_sizes, int n_in,
                              void* d_out, int out_size) {
    const float* x      = (const float*)d_in[0];
    const int*   ei     = (const int*)  d_in[1];
    const int*   batch  = (const int*)  d_in[2];
    const float* W1     = (const float*)d_in[3];
    const float* a_src1 = (const float*)d_in[4];
    const float* a_dst1 = (const float*)d_in[5];
    const float* b1     = (const float*)d_in[6];
    const float* W2     = (const float*)d_in[7];
    const float* a_src2 = (const float*)d_in[8];
    const float* a_dst2 = (const float*)d_in[9];
    const float* b2     = (const float*)d_in[10];
    const float* Wg     = (const float*)d_in[11];
    const float* bg     = (const float*)d_in[12];
    float* out = (float*)d_out;

    float *p_out1, *p_den1, *p_emax1, *p_out2, *p_den2, *p_emax2, *p_pool;
    cudaGetSymbolAddress((void**)&p_out1,  g_out1);
    cudaGetSymbolAddress((void**)&p_den1,  g_den1);
    cudaGetSymbolAddress((void**)&p_emax1, g_emax1);
    cudaGetSymbolAddress((void**)&p_out2,  g_out2);
    cudaGetSymbolAddress((void**)&p_den2,  g_den2);
    cudaGetSymbolAddress((void**)&p_emax2, g_emax2);
    cudaGetSymbolAddress((void**)&p_pool,  g_pool);
    float *p_h1;
    cudaGetSymbolAddress((void**)&p_h1, g_h1);
    float *p_ho1;  // gemm2 input = g_out1 (post-ELU)
    p_ho1 = p_out1;
    float *p_h2;
    cudaGetSymbolAddress((void**)&p_h2, g_h2);

    const int TB = 256;
    auto nb = [](long n, int t) { return (int)((n + t - 1) / t); };

    // ---- layer 1 ----
    {
        dim3 g(nb(HF, BN), nb(N_NODES, BM));
        gemm64<<<g, 256>>>(x, W1, p_h1, N_NODES, HF, F_IN);
    }
    alpha1_kernel<<<nb((long)N_NODES * 32, TB), TB>>>(a_src1, a_dst1);
    fill_kernel<<<nb(N_NODES * HEADS, TB), TB>>>(p_emax1, -1e30f, N_NODES * HEADS);
    fill_kernel<<<nb(N_NODES * HEADS, TB), TB>>>(p_den1, 0.f, N_NODES * HEADS);
    fill_kernel<<<nb((long)N_NODES * HF, TB), TB>>>(p_out1, 0.f, N_NODES * HF);
    edge_max1<<<nb((long)ET * HEADS, TB), TB>>>(ei);
    edge_exp1<<<nb((long)ET * HEADS, TB), TB>>>(ei);
    scatter1<<<ET, 256>>>(ei);
    elu1_kernel<<<nb((long)N_NODES * HF, TB), TB>>>(b1);

    // ---- layer 2 ----
    {
        dim3 g(nb(OUT_DIM, BN), nb(N_NODES, BM));
        gemm64<<<g, 256>>>(p_ho1, W2, p_h2, N_NODES, OUT_DIM, HF);
    }
    alpha2_kernel<<<nb((long)N_NODES * 32, TB), TB>>>(a_src2, a_dst2);
    fill_kernel<<<nb(N_NODES, TB), TB>>>(p_emax2, -1e30f, N_NODES);
    fill_kernel<<<nb(N_NODES, TB), TB>>>(p_den2, 0.f, N_NODES);
    fill_kernel<<<nb((long)N_NODES * OUT_DIM, TB), TB>>>(p_out2, 0.f, N_NODES * OUT_DIM);
    edge_max2<<<nb(ET, TB), TB>>>(ei);
    edge_exp2<<<nb(ET, TB), TB>>>(ei);
    scatter2<<<ET, 128>>>(ei);

    // ---- pool + head ----
    fill_kernel<<<nb(N_GRAPHS * OUT_DIM, TB), TB>>>(p_pool, 0.f, N_GRAPHS * OUT_DIM);
    pool_kernel<<<nb((long)N_NODES * OUT_DIM, TB), TB>>>(b2, batch);
    final_kernel<<<N_GRAPHS, OUT_DIM>>>(Wg, bg, out);
}

// round 2
// speedup vs baseline: 2.4748x; 2.4748x over previous
#include <cuda_runtime.h>
#include <math.h>

#define N_NODES 20000
#define N_EDGES 256000
#define ET (N_EDGES + N_NODES)   // with self loops = 276000
#define N_GRAPHS 512
#define F_IN 75
#define KP1 80                   // padded F_IN
#define HEADS 10
#define HF 750
#define NP1 768                  // padded HF (also K of gemm2)
#define OUT_DIM 128

// ---------------- scratch ---------------------------------------------------
__device__ float g_xp[(size_t)N_NODES * KP1];        // padded x       6.4 MB
__device__ float g_W1p[KP1 * NP1];                   // padded W1
__device__ float g_W2p[NP1 * OUT_DIM];               // padded W2
__device__ float g_h1[(size_t)N_NODES * NP1];        // x@W1          61 MB
__device__ float g_out1[(size_t)N_NODES * NP1];      // gat1 out      61 MB
__device__ float g_h2[(size_t)N_NODES * OUT_DIM];    // out1@W2       10 MB
__device__ float g_as1[N_NODES * HEADS];
__device__ float g_ad1[N_NODES * HEADS];
__device__ float g_as2[N_NODES];
__device__ float g_ad2[N_NODES];
__device__ int   g_deg[N_NODES];
__device__ int   g_rowptr[N_NODES + 1];
__device__ int   g_cur[N_NODES];
__device__ int   g_col[ET];
__device__ float g_pool[N_GRAPHS * OUT_DIM];

// ---------------- helpers ---------------------------------------------------
__device__ __forceinline__ void edge_sd(const int* __restrict__ ei, int e,
                                        int& s, int& d) {
    if (e < N_EDGES) { s = ei[e]; d = ei[N_EDGES + e]; }
    else             { s = e - N_EDGES; d = s; }
}
__device__ __forceinline__ float leaky(float x) { return x > 0.f ? x : 0.2f * x; }

__global__ void fill_f(float* p, float v, int n) {
    int i = blockIdx.x * blockDim.x + threadIdx.x;
    if (i < n) p[i] = v;
}
__global__ void fill_i(int* p, int v, int n) {
    int i = blockIdx.x * blockDim.x + threadIdx.x;
    if (i < n) p[i] = v;
}

// ---------------- padding copies --------------------------------------------
__global__ void pad_x(const float* __restrict__ x) {
    int t = blockIdx.x * blockDim.x + threadIdx.x;
    if (t >= N_NODES * KP1) return;
    int n = t / KP1, k = t - n * KP1;
    g_xp[t] = (k < F_IN) ? x[n * F_IN + k] : 0.f;
}
__global__ void pad_W1(const float* __restrict__ W1) {
    int t = blockIdx.x * blockDim.x + threadIdx.x;
    if (t >= KP1 * NP1) return;
    int k = t / NP1, n = t - k * NP1;
    g_W1p[t] = (k < F_IN && n < HF) ? W1[k * HF + n] : 0.f;
}
__global__ void pad_W2(const float* __restrict__ W2) {
    int t = blockIdx.x * blockDim.x + threadIdx.x;
    if (t >= NP1 * OUT_DIM) return;
    int k = t / OUT_DIM, n = t - k * OUT_DIM;
    g_W2p[t] = (k < HF) ? W2[k * OUT_DIM + n] : 0.f;
}

// ---------------- CSR build --------------------------------------------------
__global__ void deg_count(const int* __restrict__ ei) {
    int e = blockIdx.x * blockDim.x + threadIdx.x;
    if (e >= ET) return;
    int s, d; edge_sd(ei, e, s, d);
    atomicAdd(&g_deg[d], 1);
}
// single-block scan: 1024 threads x 20 elements
__global__ __launch_bounds__(1024) void scan_deg() {
    __shared__ int ssum[1024];
    const int CH = 20;
    int tid = threadIdx.x;
    int base = tid * CH;
    int s = 0;
    #pragma unroll
    for (int i = 0; i < CH; i++) {
        int idx = base + i;
        if (idx < N_NODES) s += g_deg[idx];
    }
    ssum[tid] = s;
    __syncthreads();
    for (int off = 1; off < 1024; off <<= 1) {
        int v = (tid >= off) ? ssum[tid - off] : 0;
        __syncthreads();
        ssum[tid] += v;
        __syncthreads();
    }
    int run = tid ? ssum[tid - 1] : 0;
    #pragma unroll
    for (int i = 0; i < CH; i++) {
        int idx = base + i;
        if (idx < N_NODES) {
            g_rowptr[idx] = run;
            g_cur[idx] = run;
            run += g_deg[idx];
        }
    }
    if (tid == 1023) g_rowptr[N_NODES] = ssum[1023];
}
__global__ void scatter_ids(const int* __restrict__ ei) {
    int e = blockIdx.x * blockDim.x + threadIdx.x;
    if (e >= ET) return;
    int s, d; edge_sd(ei, e, s, d);
    int pos = atomicAdd(&g_cur[d], 1);
    g_col[pos] = s;
}

// ---------------- SGEMM: C[M,N] = A[M,K] @ B[K,N] ---------------------------
// 64x64 tile, BK=16, 64 threads, 8x8 micro-tile. K,N multiples of 16/64.
#define GBM 64
#define GBN 64
#define GBK 16
__global__ __launch_bounds__(64) void gemm_k(
    const float* __restrict__ A, const float* __restrict__ B,
    float* __restrict__ C, int M, int N, int K) {
    __shared__ float As[GBK][GBM];
    __shared__ float Bs[GBK][GBN];
    int bm = blockIdx.y * GBM, bn = blockIdx.x * GBN;
    int tid = threadIdx.x;
    int ty = tid >> 3, tx = tid & 7;
    float acc[8][8] = {};
    int arow = bm + tid;
    bool avalid = arow < M;
    const float* Aptr = A + (size_t)arow * K;
    for (int k0 = 0; k0 < K; k0 += GBK) {
        // A: thread loads its row's 16-float k-line (conflict-free STS by tid)
        float4 av[4];
        #pragma unroll
        for (int t = 0; t < 4; t++)
            av[t] = avalid ? *(const float4*)(Aptr + k0 + t * 4)
                           : make_float4(0.f, 0.f, 0.f, 0.f);
        #pragma unroll
        for (int t = 0; t < 4; t++) {
            As[t * 4 + 0][tid] = av[t].x;
            As[t * 4 + 1][tid] = av[t].y;
            As[t * 4 + 2][tid] = av[t].z;
            As[t * 4 + 3][tid] = av[t].w;
        }
        // B: 256 float4 quads, 4 per thread, coalesced rows
        #pragma unroll
        for (int t = 0; t < 4; t++) {
            int q = t * 64 + tid;
            int k = q >> 4, nq = q & 15;
            *(float4*)&Bs[k][nq * 4] =
                *(const float4*)(B + (size_t)(k0 + k) * N + bn + nq * 4);
        }
        __syncthreads();
        #pragma unroll
        for (int k = 0; k < GBK; k++) {
            float a[8], b[8];
            *(float4*)&a[0] = *(float4*)&As[k][ty * 8];
            *(float4*)&a[4] = *(float4*)&As[k][ty * 8 + 4];
            *(float4*)&b[0] = *(float4*)&Bs[k][tx * 8];
            *(float4*)&b[4] = *(float4*)&Bs[k][tx * 8 + 4];
            #pragma unroll
            for (int i = 0; i < 8; i++)
                #pragma unroll
                for (int j = 0; j < 8; j++)
                    acc[i][j] += a[i] * b[j];
        }
        __syncthreads();
    }
    #pragma unroll
    for (int i = 0; i < 8; i++) {
        int m = bm + ty * 8 + i;
        if (m >= M) continue;
        float* crow = C + (size_t)m * N + bn + tx * 8;
        *(float4*)&crow[0] = *(float4*)&acc[i][0];
        *(float4*)&crow[4] = *(float4*)&acc[i][4];
    }
}

// ---------------- attention logits -------------------------------------------
// warp per node: alpha_src / alpha_dst for all 10 heads
__global__ void alpha1_kernel(const float* __restrict__ a_src,
                              const float* __restrict__ a_dst) {
    int warp = (blockIdx.x * blockDim.x + threadIdx.x) >> 5;
    int lane = threadIdx.x & 31;
    if (warp >= N_NODES) return;
    const float* row = g_h1 + (size_t)warp * NP1;
    for (int h = 0; h < HEADS; h++) {
        float s = 0.f, d = 0.f;
        for (int f = lane; f < F_IN; f += 32) {
            float v = row[h * F_IN + f];
            s += v * a_src[h * F_IN + f];
            d += v * a_dst[h * F_IN + f];
        }
        #pragma unroll
        for (int o = 16; o > 0; o >>= 1) {
            s += __shfl_down_sync(~0u, s, o);
            d += __shfl_down_sync(~0u, d, o);
        }
        if (lane == 0) {
            g_as1[warp * HEADS + h] = s;
            g_ad1[warp * HEADS + h] = d;
        }
    }
}
__global__ void alpha2_kernel(const float* __restrict__ a_src,
                              const float* __restrict__ a_dst) {
    int warp = (blockIdx.x * blockDim.x + threadIdx.x) >> 5;
    int lane = threadIdx.x & 31;
    if (warp >= N_NODES) return;
    const float* row = g_h2 + (size_t)warp * OUT_DIM;
    float s = 0.f, d = 0.f;
    #pragma unroll
    for (int f = lane; f < OUT_DIM; f += 32) {
        float v = row[f];
        s += v * a_src[f];
        d += v * a_dst[f];
    }
    #pragma unroll
    for (int o = 16; o > 0; o >>= 1) {
        s += __shfl_down_sync(~0u, s, o);
        d += __shfl_down_sync(~0u, d, o);
    }
    if (lane == 0) { g_as2[warp] = s; g_ad2[warp] = d; }
}

// ---------------- layer-1 aggregation (CSR gather, softmax w/o max-shift) ---
// one block (256 thr) per dst node; out1 = ELU(sum_j w_j*h1[src_j]/den + b1)
#define CAP1 64
__global__ __launch_bounds__(256) void agg1_kernel(const float* __restrict__ b1) {
    int d = blockIdx.x;
    int tid = threadIdx.x;
    __shared__ int   csm[CAP1];
    __shared__ float wsm[CAP1 * HEADS];
    __shared__ float den[HEADS];
    __shared__ float adc[HEADS];
    if (tid < HEADS) {
        adc[tid] = g_ad1[d * HEADS + tid];
        den[tid] = 0.f;
    }
    int start = g_rowptr[d], end = g_rowptr[d + 1];
    float acc0 = 0.f, acc1 = 0.f, acc2 = 0.f;
    int f0 = tid, f1 = tid + 256, f2 = tid + 512;
    int h0 = f0 / F_IN, h1i = f1 / F_IN, h2i = f2 < HF ? f2 / F_IN : 0;
    for (int p = start; p < end; p += CAP1) {
        int nc = min(CAP1, end - p);
        __syncthreads();                 // protect csm/wsm reuse
        if (tid < nc) csm[tid] = g_col[p + tid];
        __syncthreads();
        for (int idx = tid; idx < nc * HEADS; idx += 256) {
            int j = idx / HEADS, h = idx - j * HEADS;
            float e = leaky(g_as1[csm[j] * HEADS + h] + adc[h]);
            float w = __expf(e);
            wsm[idx] = w;
            atomicAdd(&den[h], w);
        }
        __syncthreads();
        for (int j = 0; j < nc; j++) {
            const float* hr = g_h1 + (size_t)csm[j] * NP1;
            const float* wj = wsm + j * HEADS;
            acc0 += hr[f0] * wj[h0];
            acc1 += hr[f1] * wj[h1i];
            if (f2 < HF) acc2 += hr[f2] * wj[h2i];
        }
    }
    __syncthreads();
    float* orow = g_out1 + (size_t)d * NP1;
    {
        float v = acc0 / (den[h0] + 1e-16f) + b1[f0];
        orow[f0] = v > 0.f ? v : __expf(v) - 1.f;
        v = acc1 / (den[h1i] + 1e-16f) + b1[f1];
        orow[f1] = v > 0.f ? v : __expf(v) - 1.f;
        if (f2 < HF) {
            v = acc2 / (den[h2i] + 1e-16f) + b1[f2];
            orow[f2] = v > 0.f ? v : __expf(v) - 1.f;
        } else {
            orow[f2] = 0.f;   // padding cols 750..767 must be zero for gemm2
        }
    }
}

// ---------------- layer-2 aggregation + ReLU + graph max-pool ----------------
#define CAP2 128
__global__ __launch_bounds__(128) void agg2_kernel(
    const float* __restrict__ b2, const int* __restrict__ batch) {
    int d = blockIdx.x;
    int tid = threadIdx.x;
    __shared__ int   csm[CAP2];
    __shared__ float wsm[CAP2];
    __shared__ float den;
    if (tid == 0) den = 0.f;
    float ad = g_ad2[d];
    int start = g_rowptr[d], end = g_rowptr[d + 1];
    float acc = 0.f;
    for (int p = start; p < end; p += CAP2) {
        int nc = min(CAP2, end - p);
        __syncthreads();
        if (tid < nc) {
            int s = g_col[p + tid];
            csm[tid] = s;
            float w = __expf(leaky(g_as2[s] + ad));
            wsm[tid] = w;
            atomicAdd(&den, w);
        }
        __syncthreads();
        for (int j = 0; j < nc; j++)
            acc += g_h2[(size_t)csm[j] * OUT_DIM + tid] * wsm[j];
    }
    __syncthreads();
    float v = acc / (den + 1e-16f) + b2[tid];
    v = v > 0.f ? v : 0.f;
    int gi = batch[d];
    atomicMax((int*)&g_pool[gi * OUT_DIM + tid], __float_as_int(v));
}

// ---------------- head: relu(pool @ Wg + bg) ---------------------------------
__global__ __launch_bounds__(128) void final_kernel(
    const float* __restrict__ Wg, const float* __restrict__ bg,
    float* __restrict__ out) {
    __shared__ float gr[OUT_DIM];
    int gi = blockIdx.x, j = threadIdx.x;
    gr[j] = g_pool[gi * OUT_DIM + j];
    __syncthreads();
    float acc = bg[j];
    #pragma unroll 8
    for (int k = 0; k < OUT_DIM; k++)
        acc += gr[k] * Wg[k * OUT_DIM + j];
    out[gi * OUT_DIM + j] = acc > 0.f ? acc : 0.f;
}

// ---------------- launch ------------------------------------------------------
extern "C" void kernel_launch(void* const* d_in, const int* in_sizes, int n_in,
                              void* d_out, int out_size) {
    const float* x      = (const float*)d_in[0];
    const int*   ei     = (const int*)  d_in[1];
    const int*   batch  = (const int*)  d_in[2];
    const float* W1     = (const float*)d_in[3];
    const float* a_src1 = (const float*)d_in[4];
    const float* a_dst1 = (const float*)d_in[5];
    const float* b1     = (const float*)d_in[6];
    const float* W2     = (const float*)d_in[7];
    const float* a_src2 = (const float*)d_in[8];
    const float* a_dst2 = (const float*)d_in[9];
    const float* b2     = (const float*)d_in[10];
    const float* Wg     = (const float*)d_in[11];
    const float* bg     = (const float*)d_in[12];
    float* out = (float*)d_out;

    float *p_xp, *p_W1p, *p_W2p, *p_h1, *p_out1, *p_h2, *p_pool;
    int *p_deg;
    cudaGetSymbolAddress((void**)&p_xp,   g_xp);
    cudaGetSymbolAddress((void**)&p_W1p,  g_W1p);
    cudaGetSymbolAddress((void**)&p_W2p,  g_W2p);
    cudaGetSymbolAddress((void**)&p_h1,   g_h1);
    cudaGetSymbolAddress((void**)&p_out1, g_out1);
    cudaGetSymbolAddress((void**)&p_h2,   g_h2);
    cudaGetSymbolAddress((void**)&p_pool, g_pool);
    cudaGetSymbolAddress((void**)&p_deg,  g_deg);

    const int TB = 256;
    auto nb = [](long n, int t) { return (int)((n + t - 1) / t); };

    // padding copies + degree count (launches 1..5)
    pad_x <<<nb((long)N_NODES * KP1, TB), TB>>>(x);
    pad_W1<<<nb(KP1 * NP1, TB), TB>>>(W1);
    pad_W2<<<nb(NP1 * OUT_DIM, TB), TB>>>(W2);
    fill_i<<<nb(N_NODES, TB), TB>>>(p_deg, 0, N_NODES);
    deg_count<<<nb(ET, TB), TB>>>(ei);

    // gemm1: h1 = xp @ W1p   (launch 6 -> ncu -s 5 profiles this)
    {
        dim3 g(NP1 / GBN, nb(N_NODES, GBM));
        gemm_k<<<g, 64>>>(p_xp, p_W1p, p_h1, N_NODES, NP1, KP1);
    }

    // finish CSR
    scan_deg<<<1, 1024>>>();
    scatter_ids<<<nb(ET, TB), TB>>>(ei);
    fill_f<<<nb(N_GRAPHS * OUT_DIM, TB), TB>>>(p_pool, 0.f, N_GRAPHS * OUT_DIM);

    // layer 1 attention + aggregation
    alpha1_kernel<<<nb((long)N_NODES * 32, TB), TB>>>(a_src1, a_dst1);
    agg1_kernel<<<N_NODES, 256>>>(b1);

    // gemm2: h2 = out1 @ W2p
    {
        dim3 g(OUT_DIM / GBN, nb(N_NODES, GBM));
        gemm_k<<<g, 64>>>(p_out1, p_W2p, p_h2, N_NODES, OUT_DIM, NP1);
    }

    // layer 2 attention + aggregation (+ fused ReLU + max-pool)
    alpha2_kernel<<<nb((long)N_NODES * 32, TB), TB>>>(a_src2, a_dst2);
    agg2_kernel<<<N_NODES, 128>>>(b2, batch);

    // head
    final_kernel<<<N_GRAPHS, OUT_DIM>>>(Wg, bg, out);
}

// round 3
// speedup vs baseline: 3.0517x; 1.2331x over previous
#include <cuda_runtime.h>
#include <math.h>
#include <mma.h>
using namespace nvcuda;

#define N_NODES 20000
#define M_PAD 20032              // N_NODES padded to 64
#define N_EDGES 256000
#define ET (N_EDGES + N_NODES)   // with self loops = 276000
#define N_GRAPHS 512
#define F_IN 75
#define KP1 80                   // padded F_IN (mult of 16)
#define HEADS 10
#define HF 750
#define NP1 768                  // padded HF (also K of gemm2)
#define OUT_DIM 128

// ---------------- scratch ---------------------------------------------------
__device__ float g_xp[(size_t)M_PAD * KP1];          // padded x
__device__ float g_W1p[KP1 * NP1];
__device__ float g_W2p[NP1 * OUT_DIM];
__device__ float g_h1[(size_t)M_PAD * NP1];          // x@W1
__device__ float g_out1[(size_t)M_PAD * NP1];        // gat1 out
__device__ float g_h2[(size_t)M_PAD * OUT_DIM];      // out1@W2
__device__ float g_as1[N_NODES * HEADS];
__device__ float g_ad1[N_NODES * HEADS];
__device__ float g_as2[N_NODES];
__device__ float g_ad2[N_NODES];
__device__ int   g_deg[N_NODES];
__device__ int   g_rowptr[N_NODES + 1];
__device__ int   g_cur[N_NODES];
__device__ int   g_col[ET];
__device__ float g_pool[N_GRAPHS * OUT_DIM];

// ---------------- helpers ---------------------------------------------------
__device__ __forceinline__ void edge_sd(const int* __restrict__ ei, int e,
                                        int& s, int& d) {
    if (e < N_EDGES) { s = ei[e]; d = ei[N_EDGES + e]; }
    else             { s = e - N_EDGES; d = s; }
}
__device__ __forceinline__ float leaky(float x) { return x > 0.f ? x : 0.2f * x; }

__global__ void fill_f(float* p, float v, int n) {
    int i = blockIdx.x * blockDim.x + threadIdx.x;
    if (i < n) p[i] = v;
}
__global__ void fill_i(int* p, int v, int n) {
    int i = blockIdx.x * blockDim.x + threadIdx.x;
    if (i < n) p[i] = v;
}

// ---------------- padding copies --------------------------------------------
__global__ void pad_x(const float* __restrict__ x) {
    int t = blockIdx.x * blockDim.x + threadIdx.x;
    if (t >= M_PAD * KP1) return;
    int n = t / KP1, k = t - n * KP1;
    g_xp[t] = (n < N_NODES && k < F_IN) ? x[n * F_IN + k] : 0.f;
}
__global__ void pad_W1(const float* __restrict__ W1) {
    int t = blockIdx.x * blockDim.x + threadIdx.x;
    if (t >= KP1 * NP1) return;
    int k = t / NP1, n = t - k * NP1;
    g_W1p[t] = (k < F_IN && n < HF) ? W1[k * HF + n] : 0.f;
}
__global__ void pad_W2(const float* __restrict__ W2) {
    int t = blockIdx.x * blockDim.x + threadIdx.x;
    if (t >= NP1 * OUT_DIM) return;
    int k = t / OUT_DIM, n = t - k * OUT_DIM;
    g_W2p[t] = (k < HF) ? W2[k * OUT_DIM + n] : 0.f;
}

// ---------------- CSR build --------------------------------------------------
__global__ void deg_count(const int* __restrict__ ei) {
    int e = blockIdx.x * blockDim.x + threadIdx.x;
    if (e >= ET) return;
    int s, d; edge_sd(ei, e, s, d);
    atomicAdd(&g_deg[d], 1);
}
__global__ __launch_bounds__(1024) void scan_deg() {
    __shared__ int ssum[1024];
    const int CH = 20;
    int tid = threadIdx.x;
    int base = tid * CH;
    int s = 0;
    #pragma unroll
    for (int i = 0; i < CH; i++) {
        int idx = base + i;
        if (idx < N_NODES) s += g_deg[idx];
    }
    ssum[tid] = s;
    __syncthreads();
    for (int off = 1; off < 1024; off <<= 1) {
        int v = (tid >= off) ? ssum[tid - off] : 0;
        __syncthreads();
        ssum[tid] += v;
        __syncthreads();
    }
    int run = tid ? ssum[tid - 1] : 0;
    #pragma unroll
    for (int i = 0; i < CH; i++) {
        int idx = base + i;
        if (idx < N_NODES) {
            g_rowptr[idx] = run;
            g_cur[idx] = run;
            run += g_deg[idx];
        }
    }
    if (tid == 1023) g_rowptr[N_NODES] = ssum[1023];
}
__global__ void scatter_ids(const int* __restrict__ ei) {
    int e = blockIdx.x * blockDim.x + threadIdx.x;
    if (e >= ET) return;
    int s, d; edge_sd(ei, e, s, d);
    int pos = atomicAdd(&g_cur[d], 1);
    g_col[pos] = s;
}

// ---------------- TF32 tensor-core GEMM: C[M,N] = A[M,K] @ B[K,N] -----------
// 64x64 block tile, BK=16, 128 threads (4 warps x 32x32), wmma m16n16k8 tf32.
// Requires: M mult of 64, N mult of 64, K mult of 16. Row-major everything.
#define TCM 64
#define TCN 64
#define TCK 16
#define AS_LD 24   // 16 + 8 pad (96B rows, 16B-aligned)
#define BS_LD 72   // 64 + 8 pad (288B rows, 16B-aligned)
__global__ __launch_bounds__(128) void gemm_tc(
    const float* __restrict__ A, const float* __restrict__ B,
    float* __restrict__ C, int M, int N, int K) {
    __shared__ float As[TCM][AS_LD];
    __shared__ float Bs[TCK][BS_LD];
    int bm = blockIdx.y * TCM, bn = blockIdx.x * TCN;
    int tid = threadIdx.x;
    int warp = tid >> 5;
    int wm = (warp >> 1) * 32, wn = (warp & 1) * 32;

    wmma::fragment<wmma::accumulator, 16, 16, 8, float> acc[2][2];
    #pragma unroll
    for (int i = 0; i < 2; i++)
        #pragma unroll
        for (int j = 0; j < 2; j++)
            wmma::fill_fragment(acc[i][j], 0.f);

    for (int k0 = 0; k0 < K; k0 += TCK) {
        // A tile: 64x16 floats = 256 quads, 2 per thread
        #pragma unroll
        for (int t = 0; t < 2; t++) {
            int idx = t * 128 + tid;
            int r = idx >> 2, q = idx & 3;
            *(float4*)&As[r][q * 4] =
                *(const float4*)(A + (size_t)(bm + r) * K + k0 + q * 4);
        }
        // B tile: 16x64 floats = 256 quads
        #pragma unroll
        for (int t = 0; t < 2; t++) {
            int idx = t * 128 + tid;
            int r = idx >> 4, q = idx & 15;
            *(float4*)&Bs[r][q * 4] =
                *(const float4*)(B + (size_t)(k0 + r) * N + bn + q * 4);
        }
        __syncthreads();
        #pragma unroll
        for (int ks = 0; ks < 2; ks++) {
            wmma::fragment<wmma::matrix_a, 16, 16, 8,
                           wmma::precision::tf32, wmma::row_major> af[2];
            wmma::fragment<wmma::matrix_b, 16, 16, 8,
                           wmma::precision::tf32, wmma::row_major> bf[2];
            #pragma unroll
            for (int i = 0; i < 2; i++) {
                wmma::load_matrix_sync(af[i], &As[wm + i * 16][ks * 8], AS_LD);
                #pragma unroll
                for (int e = 0; e < af[i].num_elements; e++)
                    af[i].x[e] = wmma::__float_to_tf32(af[i].x[e]);
            }
            #pragma unroll
            for (int j = 0; j < 2; j++) {
                wmma::load_matrix_sync(bf[j], &Bs[ks * 8][wn + j * 16], BS_LD);
                #pragma unroll
                for (int e = 0; e < bf[j].num_elements; e++)
                    bf[j].x[e] = wmma::__float_to_tf32(bf[j].x[e]);
            }
            #pragma unroll
            for (int i = 0; i < 2; i++)
                #pragma unroll
                for (int j = 0; j < 2; j++)
                    wmma::mma_sync(acc[i][j], af[i], bf[j], acc[i][j]);
        }
        __syncthreads();
    }
    #pragma unroll
    for (int i = 0; i < 2; i++)
        #pragma unroll
        for (int j = 0; j < 2; j++)
            wmma::store_matrix_sync(
                C + (size_t)(bm + wm + i * 16) * N + bn + wn + j * 16,
                acc[i][j], N, wmma::mem_row_major);
}

// ---------------- attention logits -------------------------------------------
__global__ void alpha1_kernel(const float* __restrict__ a_src,
                              const float* __restrict__ a_dst) {
    int warp = (blockIdx.x * blockDim.x + threadIdx.x) >> 5;
    int lane = threadIdx.x & 31;
    if (warp >= N_NODES) return;
    const float* row = g_h1 + (size_t)warp * NP1;
    for (int h = 0; h < HEADS; h++) {
        float s = 0.f, d = 0.f;
        for (int f = lane; f < F_IN; f += 32) {
            float v = row[h * F_IN + f];
            s += v * a_src[h * F_IN + f];
            d += v * a_dst[h * F_IN + f];
        }
        #pragma unroll
        for (int o = 16; o > 0; o >>= 1) {
            s += __shfl_down_sync(~0u, s, o);
            d += __shfl_down_sync(~0u, d, o);
        }
        if (lane == 0) {
            g_as1[warp * HEADS + h] = s;
            g_ad1[warp * HEADS + h] = d;
        }
    }
}
__global__ void alpha2_kernel(const float* __restrict__ a_src,
                              const float* __restrict__ a_dst) {
    int warp = (blockIdx.x * blockDim.x + threadIdx.x) >> 5;
    int lane = threadIdx.x & 31;
    if (warp >= N_NODES) return;
    const float* row = g_h2 + (size_t)warp * OUT_DIM;
    float s = 0.f, d = 0.f;
    #pragma unroll
    for (int f = lane; f < OUT_DIM; f += 32) {
        float v = row[f];
        s += v * a_src[f];
        d += v * a_dst[f];
    }
    #pragma unroll
    for (int o = 16; o > 0; o >>= 1) {
        s += __shfl_down_sync(~0u, s, o);
        d += __shfl_down_sync(~0u, d, o);
    }
    if (lane == 0) { g_as2[warp] = s; g_ad2[warp] = d; }
}

// ---------------- layer-1 aggregation (CSR gather, softmax w/o max-shift) ---
#define CAP1 64
__global__ __launch_bounds__(256) void agg1_kernel(const float* __restrict__ b1) {
    int d = blockIdx.x;
    int tid = threadIdx.x;
    __shared__ int   csm[CAP1];
    __shared__ float wsm[CAP1 * HEADS];
    __shared__ float den[HEADS];
    __shared__ float adc[HEADS];
    if (tid < HEADS) {
        adc[tid] = g_ad1[d * HEADS + tid];
        den[tid] = 0.f;
    }
    int start = g_rowptr[d], end = g_rowptr[d + 1];
    float acc0 = 0.f, acc1 = 0.f, acc2 = 0.f;
    int f0 = tid, f1 = tid + 256, f2 = tid + 512;
    int h0 = f0 / F_IN, h1i = f1 / F_IN, h2i = f2 < HF ? f2 / F_IN : 0;
    for (int p = start; p < end; p += CAP1) {
        int nc = min(CAP1, end - p);
        __syncthreads();
        if (tid < nc) csm[tid] = g_col[p + tid];
        __syncthreads();
        for (int idx = tid; idx < nc * HEADS; idx += 256) {
            int j = idx / HEADS, h = idx - j * HEADS;
            float e = leaky(g_as1[csm[j] * HEADS + h] + adc[h]);
            float w = __expf(e);
            wsm[idx] = w;
            atomicAdd(&den[h], w);
        }
        __syncthreads();
        for (int j = 0; j < nc; j++) {
            const float* hr = g_h1 + (size_t)csm[j] * NP1;
            const float* wj = wsm + j * HEADS;
            acc0 += hr[f0] * wj[h0];
            acc1 += hr[f1] * wj[h1i];
            if (f2 < HF) acc2 += hr[f2] * wj[h2i];
        }
    }
    __syncthreads();
    float* orow = g_out1 + (size_t)d * NP1;
    {
        float v = acc0 / (den[h0] + 1e-16f) + b1[f0];
        orow[f0] = v > 0.f ? v : __expf(v) - 1.f;
        v = acc1 / (den[h1i] + 1e-16f) + b1[f1];
        orow[f1] = v > 0.f ? v : __expf(v) - 1.f;
        if (f2 < HF) {
            v = acc2 / (den[h2i] + 1e-16f) + b1[f2];
            orow[f2] = v > 0.f ? v : __expf(v) - 1.f;
        } else {
            orow[f2] = 0.f;   // padding cols 750..767 must be zero for gemm2
        }
    }
}

// ---------------- layer-2 aggregation + ReLU + graph max-pool ----------------
#define CAP2 128
__global__ __launch_bounds__(128) void agg2_kernel(
    const float* __restrict__ b2, const int* __restrict__ batch) {
    int d = blockIdx.x;
    int tid = threadIdx.x;
    __shared__ int   csm[CAP2];
    __shared__ float wsm[CAP2];
    __shared__ float den;
    if (tid == 0) den = 0.f;
    float ad = g_ad2[d];
    int start = g_rowptr[d], end = g_rowptr[d + 1];
    float acc = 0.f;
    for (int p = start; p < end; p += CAP2) {
        int nc = min(CAP2, end - p);
        __syncthreads();
        if (tid < nc) {
            int s = g_col[p + tid];
            csm[tid] = s;
            float w = __expf(leaky(g_as2[s] + ad));
            wsm[tid] = w;
            atomicAdd(&den, w);
        }
        __syncthreads();
        for (int j = 0; j < nc; j++)
            acc += g_h2[(size_t)csm[j] * OUT_DIM + tid] * wsm[j];
    }
    __syncthreads();
    float v = acc / (den + 1e-16f) + b2[tid];
    v = v > 0.f ? v : 0.f;
    int gi = batch[d];
    atomicMax((int*)&g_pool[gi * OUT_DIM + tid], __float_as_int(v));
}

// ---------------- head: relu(pool @ Wg + bg) ---------------------------------
__global__ __launch_bounds__(128) void final_kernel(
    const float* __restrict__ Wg, const float* __restrict__ bg,
    float* __restrict__ out) {
    __shared__ float gr[OUT_DIM];
    int gi = blockIdx.x, j = threadIdx.x;
    gr[j] = g_pool[gi * OUT_DIM + j];
    __syncthreads();
    float acc = bg[j];
    #pragma unroll 8
    for (int k = 0; k < OUT_DIM; k++)
        acc += gr[k] * Wg[k * OUT_DIM + j];
    out[gi * OUT_DIM + j] = acc > 0.f ? acc : 0.f;
}

// ---------------- launch ------------------------------------------------------
extern "C" void kernel_launch(void* const* d_in, const int* in_sizes, int n_in,
                              void* d_out, int out_size) {
    const float* x      = (const float*)d_in[0];
    const int*   ei     = (const int*)  d_in[1];
    const int*   batch  = (const int*)  d_in[2];
    const float* W1     = (const float*)d_in[3];
    const float* a_src1 = (const float*)d_in[4];
    const float* a_dst1 = (const float*)d_in[5];
    const float* b1     = (const float*)d_in[6];
    const float* W2     = (const float*)d_in[7];
    const float* a_src2 = (const float*)d_in[8];
    const float* a_dst2 = (const float*)d_in[9];
    const float* b2     = (const float*)d_in[10];
    const float* Wg     = (const float*)d_in[11];
    const float* bg     = (const float*)d_in[12];
    float* out = (float*)d_out;

    float *p_xp, *p_W1p, *p_W2p, *p_h1, *p_out1, *p_h2, *p_pool;
    int *p_deg;
    cudaGetSymbolAddress((void**)&p_xp,   g_xp);
    cudaGetSymbolAddress((void**)&p_W1p,  g_W1p);
    cudaGetSymbolAddress((void**)&p_W2p,  g_W2p);
    cudaGetSymbolAddress((void**)&p_h1,   g_h1);
    cudaGetSymbolAddress((void**)&p_out1, g_out1);
    cudaGetSymbolAddress((void**)&p_h2,   g_h2);
    cudaGetSymbolAddress((void**)&p_pool, g_pool);
    cudaGetSymbolAddress((void**)&p_deg,  g_deg);

    const int TB = 256;
    auto nb = [](long n, int t) { return (int)((n + t - 1) / t); };

    pad_x <<<nb((long)M_PAD * KP1, TB), TB>>>(x);
    pad_W1<<<nb(KP1 * NP1, TB), TB>>>(W1);
    pad_W2<<<nb(NP1 * OUT_DIM, TB), TB>>>(W2);
    fill_i<<<nb(N_NODES, TB), TB>>>(p_deg, 0, N_NODES);
    deg_count<<<nb(ET, TB), TB>>>(ei);

    // gemm1: h1 = xp @ W1p  (tensor-core TF32)
    {
        dim3 g(NP1 / TCN, M_PAD / TCM);
        gemm_tc<<<g, 128>>>(p_xp, p_W1p, p_h1, M_PAD, NP1, KP1);
    }

    // finish CSR
    scan_deg<<<1, 1024>>>();
    scatter_ids<<<nb(ET, TB), TB>>>(ei);
    fill_f<<<nb(N_GRAPHS * OUT_DIM, TB), TB>>>(p_pool, 0.f, N_GRAPHS * OUT_DIM);

    // layer 1 attention + aggregation
    alpha1_kernel<<<nb((long)N_NODES * 32, TB), TB>>>(a_src1, a_dst1);
    agg1_kernel<<<N_NODES, 256>>>(b1);

    // gemm2: h2 = out1 @ W2p  (tensor-core TF32)
    {
        dim3 g(OUT_DIM / TCN, M_PAD / TCM);
        gemm_tc<<<g, 128>>>(p_out1, p_W2p, p_h2, M_PAD, OUT_DIM, NP1);
    }

    // layer 2 attention + aggregation (+ fused ReLU + max-pool)
    alpha2_kernel<<<nb((long)N_NODES * 32, TB), TB>>>(a_src2, a_dst2);
    agg2_kernel<<<N_NODES, 128>>>(b2, batch);

    // head
    final_kernel<<<N_GRAPHS, OUT_DIM>>>(Wg, bg, out);
}

// round 4
// speedup vs baseline: 4.3911x; 1.4389x over previous
#include <cuda_runtime.h>
#include <cuda_fp16.h>
#include <math.h>
#include <mma.h>
using namespace nvcuda;

#define N_NODES 20000
#define M_PAD 20096              // N_NODES padded to 128
#define N_EDGES 256000
#define ET (N_EDGES + N_NODES)   // with self loops = 276000
#define N_GRAPHS 512
#define F_IN 75
#define KP1 80                   // padded F_IN (mult of 16)
#define HEADS 10
#define HF 750
#define NP1 768                  // padded HF (also K of gemm2)
#define NP1_2 (NP1 / 2)          // 384 half2
#define OUT_DIM 128

// ---------------- scratch ---------------------------------------------------
__device__ __half g_xh[(size_t)M_PAD * KP1];
__device__ __half g_W1h[KP1 * NP1];
__device__ __half g_W2h[NP1 * OUT_DIM];
__device__ __half g_h1h[(size_t)M_PAD * NP1];        // x@W1 (fp16)
__device__ __half g_out1h[(size_t)M_PAD * NP1];      // gat1 out (fp16)
__device__ __half g_h2h[(size_t)M_PAD * OUT_DIM];    // out1@W2 (fp16)
__device__ float g_as1[N_NODES * HEADS];
__device__ float g_ad1[N_NODES * HEADS];
__device__ float g_as2[N_NODES];
__device__ float g_ad2[N_NODES];
__device__ int   g_deg[N_NODES];
__device__ int   g_rowptr[N_NODES + 1];
__device__ int   g_cur[N_NODES];
__device__ int   g_col[ET];
__device__ float g_pool[N_GRAPHS * OUT_DIM];

// ---------------- helpers ---------------------------------------------------
__device__ __forceinline__ void edge_sd(const int* __restrict__ ei, int e,
                                        int& s, int& d) {
    if (e < N_EDGES) { s = ei[e]; d = ei[N_EDGES + e]; }
    else             { s = e - N_EDGES; d = s; }
}
__device__ __forceinline__ float leaky(float x) { return x > 0.f ? x : 0.2f * x; }

// ---------------- fused pad / convert / zero ---------------------------------
__global__ void pad_all(const float* __restrict__ x,
                        const float* __restrict__ W1,
                        const float* __restrict__ W2) {
    const int S0 = M_PAD * KP1;          // g_xh
    const int S1 = KP1 * NP1;            // g_W1h
    const int S2 = NP1 * OUT_DIM;        // g_W2h
    const int S3 = N_NODES;              // deg = 0
    const int S4 = N_GRAPHS * OUT_DIM;   // pool = 0
    int t = blockIdx.x * blockDim.x + threadIdx.x;
    if (t < S0) {
        int n = t / KP1, k = t - n * KP1;
        g_xh[t] = __float2half((n < N_NODES && k < F_IN) ? x[n * F_IN + k] : 0.f);
        return;
    }
    t -= S0;
    if (t < S1) {
        int k = t / NP1, n = t - k * NP1;
        g_W1h[t] = __float2half((k < F_IN && n < HF) ? W1[k * HF + n] : 0.f);
        return;
    }
    t -= S1;
    if (t < S2) {
        int k = t / OUT_DIM, n = t - k * OUT_DIM;
        g_W2h[t] = __float2half((k < HF) ? W2[k * OUT_DIM + n] : 0.f);
        return;
    }
    t -= S2;
    if (t < S3) { g_deg[t] = 0; return; }
    t -= S3;
    if (t < S4) g_pool[t] = 0.f;
}
#define PAD_TOTAL (M_PAD * KP1 + KP1 * NP1 + NP1 * OUT_DIM + N_NODES + N_GRAPHS * OUT_DIM)

// ---------------- CSR build --------------------------------------------------
__global__ void deg_count(const int* __restrict__ ei) {
    int e = blockIdx.x * blockDim.x + threadIdx.x;
    if (e >= ET) return;
    int s, d; edge_sd(ei, e, s, d);
    atomicAdd(&g_deg[d], 1);
}
__global__ __launch_bounds__(1024) void scan_deg() {
    __shared__ int ssum[1024];
    const int CH = 20;
    int tid = threadIdx.x;
    int base = tid * CH;
    int s = 0;
    #pragma unroll
    for (int i = 0; i < CH; i++) {
        int idx = base + i;
        if (idx < N_NODES) s += g_deg[idx];
    }
    ssum[tid] = s;
    __syncthreads();
    for (int off = 1; off < 1024; off <<= 1) {
        int v = (tid >= off) ? ssum[tid - off] : 0;
        __syncthreads();
        ssum[tid] += v;
        __syncthreads();
    }
    int run = tid ? ssum[tid - 1] : 0;
    #pragma unroll
    for (int i = 0; i < CH; i++) {
        int idx = base + i;
        if (idx < N_NODES) {
            g_rowptr[idx] = run;
            g_cur[idx] = run;
            run += g_deg[idx];
        }
    }
    if (tid == 1023) g_rowptr[N_NODES] = ssum[1023];
}
__global__ void scatter_ids(const int* __restrict__ ei) {
    int e = blockIdx.x * blockDim.x + threadIdx.x;
    if (e >= ET) return;
    int s, d; edge_sd(ei, e, s, d);
    int pos = atomicAdd(&g_cur[d], 1);
    g_col[pos] = s;
}

// ---------------- fp16 tensor-core GEMM: C[M,N] = A[M,K] @ B[K,N] -----------
// 128x64 block tile, BK=16, 256 threads (8 warps, 4x2 of 32x32), fp32 accum,
// fp16 output via per-warp smem staging. M%128==0, N%64==0, K%16==0.
#define HBM 128
#define HBN 64
#define HBK 16
#define A_LD 24
#define B_LD 72
#define P_LD 36
__global__ __launch_bounds__(256) void gemm_h(
    const __half* __restrict__ A, const __half* __restrict__ B,
    __half* __restrict__ C, int M, int N, int K) {
    __shared__ __half As[HBM][A_LD];         // 6144 B
    __shared__ __half Bs[HBK][B_LD];         // 2304 B
    __shared__ float  Ps[8][32 * P_LD];      // 36864 B
    int bm = blockIdx.y * HBM, bn = blockIdx.x * HBN;
    int tid = threadIdx.x, warp = tid >> 5, lane = tid & 31;
    int wm = (warp >> 1) * 32, wn = (warp & 1) * 32;

    wmma::fragment<wmma::accumulator, 16, 16, 16, float> acc[2][2];
    #pragma unroll
    for (int i = 0; i < 2; i++)
        #pragma unroll
        for (int j = 0; j < 2; j++)
            wmma::fill_fragment(acc[i][j], 0.f);

    for (int k0 = 0; k0 < K; k0 += HBK) {
        // A tile: 128x16 halves = 256 float4
        {
            int r = tid >> 1, q = tid & 1;
            *(float4*)&As[r][q * 8] =
                *(const float4*)(A + (size_t)(bm + r) * K + k0 + q * 8);
        }
        // B tile: 16x64 halves = 128 float4
        if (tid < 128) {
            int r = tid >> 3, q = tid & 7;
            *(float4*)&Bs[r][q * 8] =
                *(const float4*)(B + (size_t)(k0 + r) * N + bn + q * 8);
        }
        __syncthreads();
        wmma::fragment<wmma::matrix_a, 16, 16, 16, __half, wmma::row_major> af[2];
        wmma::fragment<wmma::matrix_b, 16, 16, 16, __half, wmma::row_major> bf[2];
        #pragma unroll
        for (int i = 0; i < 2; i++)
            wmma::load_matrix_sync(af[i], &As[wm + i * 16][0], A_LD);
        #pragma unroll
        for (int j = 0; j < 2; j++)
            wmma::load_matrix_sync(bf[j], &Bs[0][wn + j * 16], B_LD);
        #pragma unroll
        for (int i = 0; i < 2; i++)
            #pragma unroll
            for (int j = 0; j < 2; j++)
                wmma::mma_sync(acc[i][j], af[i], bf[j], acc[i][j]);
        __syncthreads();
    }
    // epilogue: fp32 accum -> smem -> coalesced half2 stores
    float* patch = &Ps[warp][0];
    #pragma unroll
    for (int i = 0; i < 2; i++)
        #pragma unroll
        for (int j = 0; j < 2; j++)
            wmma::store_matrix_sync(&patch[i * 16 * P_LD + j * 16], acc[i][j],
                                    P_LD, wmma::mem_row_major);
    __syncwarp();
    #pragma unroll
    for (int rr = 0; rr < 16; rr++) {
        int r = rr * 2 + (lane >> 4);
        int c2 = lane & 15;
        float v0 = patch[r * P_LD + c2 * 2];
        float v1 = patch[r * P_LD + c2 * 2 + 1];
        *(__half2*)(C + (size_t)(bm + wm + r) * N + bn + wn + c2 * 2) =
            __floats2half2_rn(v0, v1);
    }
}

// ---------------- attention logits -------------------------------------------
__global__ void alpha1_kernel(const float* __restrict__ a_src,
                              const float* __restrict__ a_dst) {
    int warp = (blockIdx.x * blockDim.x + threadIdx.x) >> 5;
    int lane = threadIdx.x & 31;
    if (warp >= N_NODES) return;
    const __half* row = g_h1h + (size_t)warp * NP1;
    for (int h = 0; h < HEADS; h++) {
        float s = 0.f, d = 0.f;
        for (int f = lane; f < F_IN; f += 32) {
            float v = __half2float(row[h * F_IN + f]);
            s += v * a_src[h * F_IN + f];
            d += v * a_dst[h * F_IN + f];
        }
        #pragma unroll
        for (int o = 16; o > 0; o >>= 1) {
            s += __shfl_down_sync(~0u, s, o);
            d += __shfl_down_sync(~0u, d, o);
        }
        if (lane == 0) {
            g_as1[warp * HEADS + h] = s;
            g_ad1[warp * HEADS + h] = d;
        }
    }
}
__global__ void alpha2_kernel(const float* __restrict__ a_src,
                              const float* __restrict__ a_dst) {
    int warp = (blockIdx.x * blockDim.x + threadIdx.x) >> 5;
    int lane = threadIdx.x & 31;
    if (warp >= N_NODES) return;
    const __half* row = g_h2h + (size_t)warp * OUT_DIM;
    float s = 0.f, d = 0.f;
    #pragma unroll
    for (int f = lane; f < OUT_DIM; f += 32) {
        float v = __half2float(row[f]);
        s += v * a_src[f];
        d += v * a_dst[f];
    }
    #pragma unroll
    for (int o = 16; o > 0; o >>= 1) {
        s += __shfl_down_sync(~0u, s, o);
        d += __shfl_down_sync(~0u, d, o);
    }
    if (lane == 0) { g_as2[warp] = s; g_ad2[warp] = d; }
}

// ---------------- layer-1 aggregation (fp16 gather, fp32 accum) --------------
// 192 threads per dst node: thread owns half2 cols {tid, tid+192} of 384.
#define CAP1 64
__global__ __launch_bounds__(192) void agg1_kernel(const float* __restrict__ b1) {
    int d = blockIdx.x;
    int tid = threadIdx.x;
    __shared__ int   csm[CAP1];
    __shared__ float wsm[CAP1 * HEADS];
    __shared__ float den[HEADS];
    __shared__ float adc[HEADS];
    if (tid < HEADS) {
        adc[tid] = g_ad1[d * HEADS + tid];
        den[tid] = 0.f;
    }
    int i0 = tid, i1 = tid + 192;
    int c0 = 2 * i0, c1 = 2 * i1;
    int h00 = min(c0 / F_IN, HEADS - 1), h01 = min((c0 + 1) / F_IN, HEADS - 1);
    int h10 = min(c1 / F_IN, HEADS - 1), h11 = min((c1 + 1) / F_IN, HEADS - 1);
    const __half2* H1 = (const __half2*)g_h1h;

    int start = g_rowptr[d], end = g_rowptr[d + 1];
    float2 acc0 = {0.f, 0.f}, acc1 = {0.f, 0.f};
    for (int p = start; p < end; p += CAP1) {
        int nc = min(CAP1, end - p);
        __syncthreads();
        if (tid < nc) csm[tid] = g_col[p + tid];
        __syncthreads();
        for (int idx = tid; idx < nc * HEADS; idx += 192) {
            int j = idx / HEADS, h = idx - j * HEADS;
            float e = leaky(g_as1[csm[j] * HEADS + h] + adc[h]);
            float w = __expf(e);
            wsm[idx] = w;
            atomicAdd(&den[h], w);
        }
        __syncthreads();
        for (int j = 0; j < nc; j++) {
            const __half2* hr = H1 + (size_t)csm[j] * NP1_2;
            const float* wj = wsm + j * HEADS;
            float2 v0 = __half22float2(hr[i0]);
            float2 v1 = __half22float2(hr[i1]);
            acc0.x += v0.x * wj[h00];
            acc0.y += v0.y * wj[h01];
            acc1.x += v1.x * wj[h10];
            acc1.y += v1.y * wj[h11];
        }
    }
    __syncthreads();
    __half2* orow = (__half2*)(g_out1h + (size_t)d * NP1);
    {
        float vx = acc0.x / (den[h00] + 1e-16f) + b1[c0];
        float vy = acc0.y / (den[h01] + 1e-16f) + b1[c0 + 1];
        vx = vx > 0.f ? vx : __expf(vx) - 1.f;
        vy = vy > 0.f ? vy : __expf(vy) - 1.f;
        orow[i0] = __floats2half2_rn(vx, vy);
    }
    if (c1 < HF) {
        float vx = acc1.x / (den[h10] + 1e-16f) + b1[c1];
        float vy = acc1.y / (den[h11] + 1e-16f) + b1[c1 + 1];
        vx = vx > 0.f ? vx : __expf(vx) - 1.f;
        vy = vy > 0.f ? vy : __expf(vy) - 1.f;
        orow[i1] = __floats2half2_rn(vx, vy);
    } else {
        orow[i1] = __floats2half2_rn(0.f, 0.f);   // pad cols 750..767
    }
}

// ---------------- layer-2 aggregation + ReLU + graph max-pool ----------------
#define CAP2 128
__global__ __launch_bounds__(128) void agg2_kernel(
    const float* __restrict__ b2, const int* __restrict__ batch) {
    int d = blockIdx.x;
    int tid = threadIdx.x;
    __shared__ int   csm[CAP2];
    __shared__ float wsm[CAP2];
    __shared__ float den;
    if (tid == 0) den = 0.f;
    float ad = g_ad2[d];
    int start = g_rowptr[d], end = g_rowptr[d + 1];
    float acc = 0.f;
    for (int p = start; p < end; p += CAP2) {
        int nc = min(CAP2, end - p);
        __syncthreads();
        if (tid < nc) {
            int s = g_col[p + tid];
            csm[tid] = s;
            float w = __expf(leaky(g_as2[s] + ad));
            wsm[tid] = w;
            atomicAdd(&den, w);
        }
        __syncthreads();
        for (int j = 0; j < nc; j++)
            acc += __half2float(g_h2h[(size_t)csm[j] * OUT_DIM + tid]) * wsm[j];
    }
    __syncthreads();
    float v = acc / (den + 1e-16f) + b2[tid];
    v = v > 0.f ? v : 0.f;
    int gi = batch[d];
    atomicMax((int*)&g_pool[gi * OUT_DIM + tid], __float_as_int(v));
}

// ---------------- head: relu(pool @ Wg + bg) ---------------------------------
__global__ __launch_bounds__(128) void final_kernel(
    const float* __restrict__ Wg, const float* __restrict__ bg,
    float* __restrict__ out) {
    __shared__ float gr[OUT_DIM];
    int gi = blockIdx.x, j = threadIdx.x;
    gr[j] = g_pool[gi * OUT_DIM + j];
    __syncthreads();
    float acc = bg[j];
    #pragma unroll 8
    for (int k = 0; k < OUT_DIM; k++)
        acc += gr[k] * Wg[k * OUT_DIM + j];
    out[gi * OUT_DIM + j] = acc > 0.f ? acc : 0.f;
}

// ---------------- launch ------------------------------------------------------
extern "C" void kernel_launch(void* const* d_in, const int* in_sizes, int n_in,
                              void* d_out, int out_size) {
    const float* x      = (const float*)d_in[0];
    const int*   ei     = (const int*)  d_in[1];
    const int*   batch  = (const int*)  d_in[2];
    const float* W1     = (const float*)d_in[3];
    const float* a_src1 = (const float*)d_in[4];
    const float* a_dst1 = (const float*)d_in[5];
    const float* b1     = (const float*)d_in[6];
    const float* W2     = (const float*)d_in[7];
    const float* a_src2 = (const float*)d_in[8];
    const float* a_dst2 = (const float*)d_in[9];
    const float* b2     = (const float*)d_in[10];
    const float* Wg     = (const float*)d_in[11];
    const float* bg     = (const float*)d_in[12];
    float* out = (float*)d_out;

    __half *p_xh, *p_W1h, *p_W2h, *p_h1h, *p_out1h, *p_h2h;
    cudaGetSymbolAddress((void**)&p_xh,    g_xh);
    cudaGetSymbolAddress((void**)&p_W1h,   g_W1h);
    cudaGetSymbolAddress((void**)&p_W2h,   g_W2h);
    cudaGetSymbolAddress((void**)&p_h1h,   g_h1h);
    cudaGetSymbolAddress((void**)&p_out1h, g_out1h);
    cudaGetSymbolAddress((void**)&p_h2h,   g_h2h);

    const int TB = 256;
    auto nb = [](long n, int t) { return (int)((n + t - 1) / t); };

    pad_all<<<nb(PAD_TOTAL, TB), TB>>>(x, W1, W2);
    deg_count<<<nb(ET, TB), TB>>>(ei);

    // gemm1: h1 = xh @ W1h  (fp16 tensor core)
    {
        dim3 g(NP1 / HBN, M_PAD / HBM);
        gemm_h<<<g, 256>>>(p_xh, p_W1h, p_h1h, M_PAD, NP1, KP1);
    }

    scan_deg<<<1, 1024>>>();
    scatter_ids<<<nb(ET, TB), TB>>>(ei);

    alpha1_kernel<<<nb((long)N_NODES * 32, TB), TB>>>(a_src1, a_dst1);
    agg1_kernel<<<N_NODES, 192>>>(b1);

    // gemm2: h2 = out1 @ W2h
    {
        dim3 g(OUT_DIM / HBN, M_PAD / HBM);
        gemm_h<<<g, 256>>>(p_out1h, p_W2h, p_h2h, M_PAD, OUT_DIM, NP1);
    }

    alpha2_kernel<<<nb((long)N_NODES * 32, TB), TB>>>(a_src2, a_dst2);
    agg2_kernel<<<N_NODES, 128>>>(b2, batch);

    final_kernel<<<N_GRAPHS, OUT_DIM>>>(Wg, bg, out);
}

// round 5
// speedup vs baseline: 4.8332x; 1.1007x over previous
#include <cuda_runtime.h>
#include <cuda_fp16.h>
#include <math.h>
#include <mma.h>
using namespace nvcuda;

#define N_NODES 20000
#define M_PAD 20096              // N_NODES padded to 128
#define N_EDGES 256000
#define ET (N_EDGES + N_NODES)   // with self loops = 276000
#define N_GRAPHS 512
#define F_IN 75
#define KP1 80                   // padded F_IN (mult of 16)
#define HEADS 10
#define HF 750
#define NP1 768                  // padded HF (also K of gemm2)
#define NP1_2 (NP1 / 2)          // 384 half2
#define OUT_DIM 128

#define SCAN_B 256
#define NBLK ((N_NODES + SCAN_B - 1) / SCAN_B)   // 79

// ---------------- scratch ---------------------------------------------------
__device__ __half g_xh[(size_t)M_PAD * KP1];
__device__ __half g_W1h[KP1 * NP1];
__device__ __half g_W2h[NP1 * OUT_DIM];
__device__ __half g_h1h[(size_t)M_PAD * NP1];        // x@W1 (fp16)
__device__ __half g_out1h[(size_t)M_PAD * NP1];      // gat1 out (fp16)
__device__ __half g_h2h[(size_t)M_PAD * OUT_DIM];    // out1@W2 (fp16)
__device__ float g_was1[F_IN * HEADS];               // folded attn weights
__device__ float g_wad1[F_IN * HEADS];
__device__ float g_as1[N_NODES * HEADS];
__device__ float g_ad1[N_NODES * HEADS];
__device__ float g_as2[N_NODES];
__device__ float g_ad2[N_NODES];
__device__ int   g_deg[N_NODES];
__device__ int   g_bsum[NBLK];
__device__ int   g_boff[NBLK];
__device__ int   g_rowptr[N_NODES + 1];
__device__ int   g_cur[N_NODES];
__device__ int   g_col[ET];
__device__ float g_pool[N_GRAPHS * OUT_DIM];

// ---------------- helpers ---------------------------------------------------
__device__ __forceinline__ void edge_sd(const int* __restrict__ ei, int e,
                                        int& s, int& d) {
    if (e < N_EDGES) { s = ei[e]; d = ei[N_EDGES + e]; }
    else             { s = e - N_EDGES; d = s; }
}
__device__ __forceinline__ float leaky(float x) { return x > 0.f ? x : 0.2f * x; }

// ---------------- fused pad / convert / zero ---------------------------------
__global__ void pad_all(const float* __restrict__ x,
                        const float* __restrict__ W1,
                        const float* __restrict__ W2) {
    const int S0 = M_PAD * KP1;
    const int S1 = KP1 * NP1;
    const int S2 = NP1 * OUT_DIM;
    const int S3 = N_NODES;
    const int S4 = N_GRAPHS * OUT_DIM;
    int t = blockIdx.x * blockDim.x + threadIdx.x;
    if (t < S0) {
        int n = t / KP1, k = t - n * KP1;
        g_xh[t] = __float2half((n < N_NODES && k < F_IN) ? x[n * F_IN + k] : 0.f);
        return;
    }
    t -= S0;
    if (t < S1) {
        int k = t / NP1, n = t - k * NP1;
        g_W1h[t] = __float2half((k < F_IN && n < HF) ? W1[k * HF + n] : 0.f);
        return;
    }
    t -= S1;
    if (t < S2) {
        int k = t / OUT_DIM, n = t - k * OUT_DIM;
        g_W2h[t] = __float2half((k < HF) ? W2[k * OUT_DIM + n] : 0.f);
        return;
    }
    t -= S2;
    if (t < S3) { g_deg[t] = 0; return; }
    t -= S3;
    if (t < S4) g_pool[t] = 0.f;
}
#define PAD_TOTAL (M_PAD * KP1 + KP1 * NP1 + NP1 * OUT_DIM + N_NODES + N_GRAPHS * OUT_DIM)

// ---------------- CSR build (multi-block scan) -------------------------------
__global__ void deg_count(const int* __restrict__ ei) {
    int e = blockIdx.x * blockDim.x + threadIdx.x;
    if (e >= ET) return;
    int s, d; edge_sd(ei, e, s, d);
    atomicAdd(&g_deg[d], 1);
}
__global__ __launch_bounds__(SCAN_B) void scan_part() {
    __shared__ int red[SCAN_B / 32];
    int b = blockIdx.x, tid = threadIdx.x;
    int idx = b * SCAN_B + tid;
    int v = (idx < N_NODES) ? g_deg[idx] : 0;
    #pragma unroll
    for (int o = 16; o > 0; o >>= 1) v += __shfl_down_sync(~0u, v, o);
    if ((tid & 31) == 0) red[tid >> 5] = v;
    __syncthreads();
    if (tid < SCAN_B / 32) {
        int s = red[tid];
        #pragma unroll
        for (int o = SCAN_B / 64; o > 0; o >>= 1) s += __shfl_down_sync(~0u, s, o);
        if (tid == 0) g_bsum[b] = s;
    }
}
__global__ __launch_bounds__(128) void scan_top() {
    __shared__ int sh[NBLK];
    int tid = threadIdx.x;
    if (tid < NBLK) sh[tid] = g_bsum[tid];
    __syncthreads();
    if (tid == 0) {
        int run = 0;
        for (int i = 0; i < NBLK; i++) { g_boff[i] = run; run += sh[i]; }
        g_rowptr[N_NODES] = ET;
    }
}
__global__ __launch_bounds__(SCAN_B) void scan_down() {
    __shared__ int sh[SCAN_B];
    int b = blockIdx.x, tid = threadIdx.x;
    int idx = b * SCAN_B + tid;
    int v = (idx < N_NODES) ? g_deg[idx] : 0;
    sh[tid] = v;
    __syncthreads();
    // Hillis-Steele inclusive scan
    for (int off = 1; off < SCAN_B; off <<= 1) {
        int t = (tid >= off) ? sh[tid - off] : 0;
        __syncthreads();
        sh[tid] += t;
        __syncthreads();
    }
    if (idx < N_NODES) {
        int excl = sh[tid] - v + g_boff[b];
        g_rowptr[idx] = excl;
        g_cur[idx] = excl;
    }
}
__global__ void scatter_ids(const int* __restrict__ ei) {
    int e = blockIdx.x * blockDim.x + threadIdx.x;
    if (e >= ET) return;
    int s, d; edge_sd(ei, e, s, d);
    int pos = atomicAdd(&g_cur[d], 1);
    g_col[pos] = s;
}

// ---------------- fp16 tensor-core GEMM: C[M,N] = A[M,K] @ B[K,N] -----------
#define HBM 128
#define HBN 64
#define HBK 16
#define A_LD 24
#define B_LD 72
#define P_LD 36
__global__ __launch_bounds__(256) void gemm_h(
    const __half* __restrict__ A, const __half* __restrict__ B,
    __half* __restrict__ C, int M, int N, int K) {
    __shared__ __half As[HBM][A_LD];
    __shared__ __half Bs[HBK][B_LD];
    __shared__ float  Ps[8][32 * P_LD];
    int bm = blockIdx.y * HBM, bn = blockIdx.x * HBN;
    int tid = threadIdx.x, warp = tid >> 5, lane = tid & 31;
    int wm = (warp >> 1) * 32, wn = (warp & 1) * 32;

    wmma::fragment<wmma::accumulator, 16, 16, 16, float> acc[2][2];
    #pragma unroll
    for (int i = 0; i < 2; i++)
        #pragma unroll
        for (int j = 0; j < 2; j++)
            wmma::fill_fragment(acc[i][j], 0.f);

    for (int k0 = 0; k0 < K; k0 += HBK) {
        {
            int r = tid >> 1, q = tid & 1;
            *(float4*)&As[r][q * 8] =
                *(const float4*)(A + (size_t)(bm + r) * K + k0 + q * 8);
        }
        if (tid < 128) {
            int r = tid >> 3, q = tid & 7;
            *(float4*)&Bs[r][q * 8] =
                *(const float4*)(B + (size_t)(k0 + r) * N + bn + q * 8);
        }
        __syncthreads();
        wmma::fragment<wmma::matrix_a, 16, 16, 16, __half, wmma::row_major> af[2];
        wmma::fragment<wmma::matrix_b, 16, 16, 16, __half, wmma::row_major> bf[2];
        #pragma unroll
        for (int i = 0; i < 2; i++)
            wmma::load_matrix_sync(af[i], &As[wm + i * 16][0], A_LD);
        #pragma unroll
        for (int j = 0; j < 2; j++)
            wmma::load_matrix_sync(bf[j], &Bs[0][wn + j * 16], B_LD);
        #pragma unroll
        for (int i = 0; i < 2; i++)
            #pragma unroll
            for (int j = 0; j < 2; j++)
                wmma::mma_sync(acc[i][j], af[i], bf[j], acc[i][j]);
        __syncthreads();
    }
    float* patch = &Ps[warp][0];
    #pragma unroll
    for (int i = 0; i < 2; i++)
        #pragma unroll
        for (int j = 0; j < 2; j++)
            wmma::store_matrix_sync(&patch[i * 16 * P_LD + j * 16], acc[i][j],
                                    P_LD, wmma::mem_row_major);
    __syncwarp();
    #pragma unroll
    for (int rr = 0; rr < 16; rr++) {
        int r = rr * 2 + (lane >> 4);
        int c2 = lane & 15;
        float v0 = patch[r * P_LD + c2 * 2];
        float v1 = patch[r * P_LD + c2 * 2 + 1];
        *(__half2*)(C + (size_t)(bm + wm + r) * N + bn + wn + c2 * 2) =
            __floats2half2_rn(v0, v1);
    }
}

// ---------------- folded attention weights (layer 1) -------------------------
// w_as1[k,h] = sum_f W1[k, h*75+f] * a_src1[h,f]   (and same for dst)
__global__ void attw1_kernel(const float* __restrict__ W1,
                             const float* __restrict__ a_src,
                             const float* __restrict__ a_dst) {
    int t = blockIdx.x * blockDim.x + threadIdx.x;
    if (t >= F_IN * HEADS) return;
    int k = t / HEADS, h = t - k * HEADS;
    const float* wrow = W1 + (size_t)k * HF + h * F_IN;
    const float* as = a_src + h * F_IN;
    const float* ad = a_dst + h * F_IN;
    float s = 0.f, d = 0.f;
    #pragma unroll 5
    for (int f = 0; f < F_IN; f++) { s += wrow[f] * as[f]; d += wrow[f] * ad[f]; }
    g_was1[k * HEADS + h] = s;
    g_wad1[k * HEADS + h] = d;
}
// logits directly from fp32 x: thread per (node, head)
__global__ __launch_bounds__(256) void alpha1_kernel(const float* __restrict__ x) {
    __shared__ float ws[F_IN * HEADS], wd[F_IN * HEADS];
    int tid = threadIdx.x;
    for (int i = tid; i < F_IN * HEADS; i += 256) { ws[i] = g_was1[i]; wd[i] = g_wad1[i]; }
    __syncthreads();
    int t = blockIdx.x * 256 + tid;
    if (t >= N_NODES * HEADS) return;
    int n = t / HEADS, h = t - n * HEADS;
    const float* xr = x + (size_t)n * F_IN;
    float s = 0.f, d = 0.f;
    #pragma unroll 5
    for (int k = 0; k < F_IN; k++) {
        float xv = xr[k];
        s += xv * ws[k * HEADS + h];
        d += xv * wd[k * HEADS + h];
    }
    g_as1[t] = s;
    g_ad1[t] = d;
}

__global__ void alpha2_kernel(const float* __restrict__ a_src,
                              const float* __restrict__ a_dst) {
    int warp = (blockIdx.x * blockDim.x + threadIdx.x) >> 5;
    int lane = threadIdx.x & 31;
    if (warp >= N_NODES) return;
    const __half* row = g_h2h + (size_t)warp * OUT_DIM;
    float s = 0.f, d = 0.f;
    #pragma unroll
    for (int f = lane; f < OUT_DIM; f += 32) {
        float v = __half2float(row[f]);
        s += v * a_src[f];
        d += v * a_dst[f];
    }
    #pragma unroll
    for (int o = 16; o > 0; o >>= 1) {
        s += __shfl_down_sync(~0u, s, o);
        d += __shfl_down_sync(~0u, d, o);
    }
    if (lane == 0) { g_as2[warp] = s; g_ad2[warp] = d; }
}

// ---------------- layer-1 aggregation (fp16 gather, fp32 accum) --------------
#define CAP1 64
__global__ __launch_bounds__(192) void agg1_kernel(const float* __restrict__ b1) {
    int d = blockIdx.x;
    int tid = threadIdx.x;
    __shared__ int   csm[CAP1];
    __shared__ float wsm[CAP1 * HEADS];
    __shared__ float den[HEADS];
    __shared__ float adc[HEADS];
    if (tid < HEADS) {
        adc[tid] = g_ad1[d * HEADS + tid];
        den[tid] = 0.f;
    }
    int i0 = tid, i1 = tid + 192;
    int c0 = 2 * i0, c1 = 2 * i1;
    int h00 = min(c0 / F_IN, HEADS - 1), h01 = min((c0 + 1) / F_IN, HEADS - 1);
    int h10 = min(c1 / F_IN, HEADS - 1), h11 = min((c1 + 1) / F_IN, HEADS - 1);
    const __half2* H1 = (const __half2*)g_h1h;

    int start = g_rowptr[d], end = g_rowptr[d + 1];
    float2 acc0 = {0.f, 0.f}, acc1 = {0.f, 0.f};
    for (int p = start; p < end; p += CAP1) {
        int nc = min(CAP1, end - p);
        __syncthreads();
        if (tid < nc) csm[tid] = g_col[p + tid];
        __syncthreads();
        for (int idx = tid; idx < nc * HEADS; idx += 192) {
            int j = idx / HEADS, h = idx - j * HEADS;
            float e = leaky(g_as1[csm[j] * HEADS + h] + adc[h]);
            float w = __expf(e);
            wsm[idx] = w;
            atomicAdd(&den[h], w);
        }
        __syncthreads();
        int j = 0;
        for (; j + 1 < nc; j += 2) {
            const __half2* hrA = H1 + (size_t)csm[j] * NP1_2;
            const __half2* hrB = H1 + (size_t)csm[j + 1] * NP1_2;
            __half2 ra0 = hrA[i0], ra1 = hrA[i1];
            __half2 rb0 = hrB[i0], rb1 = hrB[i1];
            const float* wA = wsm + j * HEADS;
            const float* wB = wsm + (j + 1) * HEADS;
            float2 a0 = __half22float2(ra0), a1 = __half22float2(ra1);
            float2 b0 = __half22float2(rb0), b1 = __half22float2(rb1);
            acc0.x += a0.x * wA[h00] + b0.x * wB[h00];
            acc0.y += a0.y * wA[h01] + b0.y * wB[h01];
            acc1.x += a1.x * wA[h10] + b1.x * wB[h10];
            acc1.y += a1.y * wA[h11] + b1.y * wB[h11];
        }
        if (j < nc) {
            const __half2* hr = H1 + (size_t)csm[j] * NP1_2;
            const float* wj = wsm + j * HEADS;
            float2 v0 = __half22float2(hr[i0]);
            float2 v1 = __half22float2(hr[i1]);
            acc0.x += v0.x * wj[h00];
            acc0.y += v0.y * wj[h01];
            acc1.x += v1.x * wj[h10];
            acc1.y += v1.y * wj[h11];
        }
    }
    __syncthreads();
    __half2* orow = (__half2*)(g_out1h + (size_t)d * NP1);
    {
        float vx = acc0.x / (den[h00] + 1e-16f) + b1[c0];
        float vy = acc0.y / (den[h01] + 1e-16f) + b1[c0 + 1];
        vx = vx > 0.f ? vx : __expf(vx) - 1.f;
        vy = vy > 0.f ? vy : __expf(vy) - 1.f;
        orow[i0] = __floats2half2_rn(vx, vy);
    }
    if (c1 < HF) {
        float vx = acc1.x / (den[h10] + 1e-16f) + b1[c1];
        float vy = acc1.y / (den[h11] + 1e-16f) + b1[c1 + 1];
        vx = vx > 0.f ? vx : __expf(vx) - 1.f;
        vy = vy > 0.f ? vy : __expf(vy) - 1.f;
        orow[i1] = __floats2half2_rn(vx, vy);
    } else {
        orow[i1] = __floats2half2_rn(0.f, 0.f);
    }
}

// ---------------- layer-2 aggregation + ReLU + graph max-pool ----------------
#define CAP2 128
__global__ __launch_bounds__(128) void agg2_kernel(
    const float* __restrict__ b2, const int* __restrict__ batch) {
    int d = blockIdx.x;
    int tid = threadIdx.x;
    __shared__ int   csm[CAP2];
    __shared__ float wsm[CAP2];
    __shared__ float den;
    if (tid == 0) den = 0.f;
    float ad = g_ad2[d];
    int start = g_rowptr[d], end = g_rowptr[d + 1];
    float acc = 0.f;
    for (int p = start; p < end; p += CAP2) {
        int nc = min(CAP2, end - p);
        __syncthreads();
        if (tid < nc) {
            int s = g_col[p + tid];
            csm[tid] = s;
            float w = __expf(leaky(g_as2[s] + ad));
            wsm[tid] = w;
            atomicAdd(&den, w);
        }
        __syncthreads();
        int j = 0;
        for (; j + 1 < nc; j += 2) {
            float vA = __half2float(g_h2h[(size_t)csm[j] * OUT_DIM + tid]);
            float vB = __half2float(g_h2h[(size_t)csm[j + 1] * OUT_DIM + tid]);
            acc += vA * wsm[j] + vB * wsm[j + 1];
        }
        if (j < nc)
            acc += __half2float(g_h2h[(size_t)csm[j] * OUT_DIM + tid]) * wsm[j];
    }
    __syncthreads();
    float v = acc / (den + 1e-16f) + b2[tid];
    v = v > 0.f ? v : 0.f;
    int gi = batch[d];
    atomicMax((int*)&g_pool[gi * OUT_DIM + tid], __float_as_int(v));
}

// ---------------- head: relu(pool @ Wg + bg) ---------------------------------
__global__ __launch_bounds__(128) void final_kernel(
    const float* __restrict__ Wg, const float* __restrict__ bg,
    float* __restrict__ out) {
    __shared__ float gr[OUT_DIM];
    int gi = blockIdx.x, j = threadIdx.x;
    gr[j] = g_pool[gi * OUT_DIM + j];
    __syncthreads();
    float acc = bg[j];
    #pragma unroll 8
    for (int k = 0; k < OUT_DIM; k++)
        acc += gr[k] * Wg[k * OUT_DIM + j];
    out[gi * OUT_DIM + j] = acc > 0.f ? acc : 0.f;
}

// ---------------- launch ------------------------------------------------------
extern "C" void kernel_launch(void* const* d_in, const int* in_sizes, int n_in,
                              void* d_out, int out_size) {
    const float* x      = (const float*)d_in[0];
    const int*   ei     = (const int*)  d_in[1];
    const int*   batch  = (const int*)  d_in[2];
    const float* W1     = (const float*)d_in[3];
    const float* a_src1 = (const float*)d_in[4];
    const float* a_dst1 = (const float*)d_in[5];
    const float* b1     = (const float*)d_in[6];
    const float* W2     = (const float*)d_in[7];
    const float* a_src2 = (const float*)d_in[8];
    const float* a_dst2 = (const float*)d_in[9];
    const float* b2     = (const float*)d_in[10];
    const float* Wg     = (const float*)d_in[11];
    const float* bg     = (const float*)d_in[12];
    float* out = (float*)d_out;

    __half *p_xh, *p_W1h, *p_W2h, *p_h1h, *p_out1h, *p_h2h;
    cudaGetSymbolAddress((void**)&p_xh,    g_xh);
    cudaGetSymbolAddress((void**)&p_W1h,   g_W1h);
    cudaGetSymbolAddress((void**)&p_W2h,   g_W2h);
    cudaGetSymbolAddress((void**)&p_h1h,   g_h1h);
    cudaGetSymbolAddress((void**)&p_out1h, g_out1h);
    cudaGetSymbolAddress((void**)&p_h2h,   g_h2h);

    const int TB = 256;
    auto nb = [](long n, int t) { return (int)((n + t - 1) / t); };

    pad_all<<<nb(PAD_TOTAL, TB), TB>>>(x, W1, W2);
    deg_count<<<nb(ET, TB), TB>>>(ei);
    attw1_kernel<<<nb(F_IN * HEADS, TB), TB>>>(W1, a_src1, a_dst1);

    // gemm1: h1 = xh @ W1h  (fp16 tensor core)
    {
        dim3 g(NP1 / HBN, M_PAD / HBM);
        gemm_h<<<g, 256>>>(p_xh, p_W1h, p_h1h, M_PAD, NP1, KP1);
    }

    // CSR: multi-block scan
    scan_part<<<NBLK, SCAN_B>>>();
    scan_top<<<1, 128>>>();
    scan_down<<<NBLK, SCAN_B>>>();
    scatter_ids<<<nb(ET, TB), TB>>>(ei);

    // layer 1
    alpha1_kernel<<<nb((long)N_NODES * HEADS, TB), TB>>>(x);
    agg1_kernel<<<N_NODES, 192>>>(b1);

    // gemm2: h2 = out1 @ W2h
    {
        dim3 g(OUT_DIM / HBN, M_PAD / HBM);
        gemm_h<<<g, 256>>>(p_out1h, p_W2h, p_h2h, M_PAD, OUT_DIM, NP1);
    }

    // layer 2
    alpha2_kernel<<<nb((long)N_NODES * 32, TB), TB>>>(a_src2, a_dst2);
    agg2_kernel<<<N_NODES, 128>>>(b2, batch);

    final_kernel<<<N_GRAPHS, OUT_DIM>>>(Wg, bg, out);
}